// round 11
// baseline (speedup 1.0000x reference)
#include <cuda_runtime.h>

// GEMV: y = alpha * (A @ x) + beta * b
// A: [16384,16384] f32. RPB=1 (one contiguous row per CTA — best DRAM
// locality, R10) + two independent half-row streams per thread: 2 batched
// LDG.128 per iter, unroll 4 -> 8 loads in flight, split acc chains.
// launch_bounds(256,8) -> 32 regs, ~100% occ.

#define ROWS 16384
#define COLS 16384
#define TPB  256
#define HALF (COLS / 8)   // 2048 float4 per half-row

__global__ __launch_bounds__(TPB, 8) void gemv_kernel(
    const float* __restrict__ alpha,
    const float* __restrict__ A,
    const float* __restrict__ x,
    const float* __restrict__ beta,
    const float* __restrict__ b,
    float* __restrict__ y)
{
    const int row = blockIdx.x;
    const int tid = threadIdx.x;

    const float4* __restrict__ arow = reinterpret_cast<const float4*>(A + (size_t)row * COLS);
    const float4* __restrict__ xv   = reinterpret_cast<const float4*>(x);

    float accA = 0.0f, accB = 0.0f;

    // Two independent streams: [0, HALF) and [HALF, 2*HALF).
    // 2048/256 = 8 iterations; unroll 4.
    #pragma unroll 4
    for (int i = tid; i < HALF; i += TPB) {
        float4 a0 = __ldcs(&arow[i]);
        float4 a1 = __ldcs(&arow[i + HALF]);
        float4 v0 = __ldg(&xv[i]);
        float4 v1 = __ldg(&xv[i + HALF]);
        accA = fmaf(a0.x, v0.x, accA); accA = fmaf(a0.y, v0.y, accA);
        accA = fmaf(a0.z, v0.z, accA); accA = fmaf(a0.w, v0.w, accA);
        accB = fmaf(a1.x, v1.x, accB); accB = fmaf(a1.y, v1.y, accB);
        accB = fmaf(a1.z, v1.z, accB); accB = fmaf(a1.w, v1.w, accB);
    }

    float acc = accA + accB;

    // warp reduce
    #pragma unroll
    for (int off = 16; off > 0; off >>= 1)
        acc += __shfl_xor_sync(0xFFFFFFFFu, acc, off);

    __shared__ float warp_sums[TPB / 32];
    const int lane = tid & 31;
    const int wid  = tid >> 5;
    if (lane == 0) warp_sums[wid] = acc;
    __syncthreads();

    if (wid == 0) {
        float s = (lane < TPB / 32) ? warp_sums[lane] : 0.0f;
        #pragma unroll
        for (int off = 4; off > 0; off >>= 1)
            s += __shfl_xor_sync(0xFFFFFFFFu, s, off);
        if (lane == 0)
            y[row] = alpha[0] * s + beta[0] * b[row];
    }
}

extern "C" void kernel_launch(void* const* d_in, const int* in_sizes, int n_in,
                              void* d_out, int out_size) {
    const float* alpha = (const float*)d_in[0];
    const float* A     = (const float*)d_in[1];
    const float* x     = (const float*)d_in[2];
    const float* beta  = (const float*)d_in[3];
    const float* b     = (const float*)d_in[4];
    float* y = (float*)d_out;

    gemv_kernel<<<ROWS, TPB>>>(alpha, A, x, beta, b, y);
}

// round 12
// speedup vs baseline: 1.0154x; 1.0154x over previous
#include <cuda_runtime.h>

// GEMV: y = alpha * (A @ x) + beta * b   -- FINAL (R10 structure, measured best)
//
// A: [16384,16384] f32, read exactly once = 1.074 GB compulsory traffic.
// Measured sustainable HBM rate on this access pattern: ~7.05 TB/s (88-89% of
// spec) -> ~150 us floor. This kernel sits on it:
//  - RPB=1: each CTA streams ONE contiguous 64KB row (best DRAM sequentiality)
//  - __ldcs on A (evict-first streaming), __ldg on x (L1-resident, 64KB)
//  - unroll 4: front-batched independent LDG.128s, ample MLP
//  - __launch_bounds__(256,8): 32 regs -> 8 CTAs/SM -> ~94% occupancy
//    (occupancy was the only lever that moved DRAM%: 56%->80%, 94%->89%)
// Exhausted alternatives (all neutral or worse): RPB=2/4, LDG.256, persistent
// grid, split half-row streams, higher unroll. TMA/cp.async excluded by the
// path-independent chip LTS cap.

#define ROWS 16384
#define COLS 16384
#define TPB  256

__global__ __launch_bounds__(TPB, 8) void gemv_kernel(
    const float* __restrict__ alpha,
    const float* __restrict__ A,
    const float* __restrict__ x,
    const float* __restrict__ beta,
    const float* __restrict__ b,
    float* __restrict__ y)
{
    const int row = blockIdx.x;
    const int tid = threadIdx.x;

    const float4* __restrict__ arow = reinterpret_cast<const float4*>(A + (size_t)row * COLS);
    const float4* __restrict__ xv   = reinterpret_cast<const float4*>(x);

    float acc = 0.0f;

    // COLS/4 = 4096 float4; 256 threads -> 16 iterations; unroll 4.
    #pragma unroll 4
    for (int i = tid; i < COLS / 4; i += TPB) {
        float4 a = __ldcs(&arow[i]);
        float4 v = __ldg(&xv[i]);
        acc = fmaf(a.x, v.x, acc);
        acc = fmaf(a.y, v.y, acc);
        acc = fmaf(a.z, v.z, acc);
        acc = fmaf(a.w, v.w, acc);
    }

    // warp reduce
    #pragma unroll
    for (int off = 16; off > 0; off >>= 1)
        acc += __shfl_xor_sync(0xFFFFFFFFu, acc, off);

    __shared__ float warp_sums[TPB / 32];
    const int lane = tid & 31;
    const int wid  = tid >> 5;
    if (lane == 0) warp_sums[wid] = acc;
    __syncthreads();

    if (wid == 0) {
        float s = (lane < TPB / 32) ? warp_sums[lane] : 0.0f;
        #pragma unroll
        for (int off = 4; off > 0; off >>= 1)
            s += __shfl_xor_sync(0xFFFFFFFFu, s, off);
        if (lane == 0)
            y[row] = alpha[0] * s + beta[0] * b[row];
    }
}

extern "C" void kernel_launch(void* const* d_in, const int* in_sizes, int n_in,
                              void* d_out, int out_size) {
    const float* alpha = (const float*)d_in[0];
    const float* A     = (const float*)d_in[1];
    const float* x     = (const float*)d_in[2];
    const float* beta  = (const float*)d_in[3];
    const float* b     = (const float*)d_in[4];
    float* y = (float*)d_out;

    gemv_kernel<<<ROWS, TPB>>>(alpha, A, x, beta, b, y);
}